// round 13
// baseline (speedup 1.0000x reference)
#include <cuda_runtime.h>
#include <cuda_fp16.h>
#include <cstdint>

#define NN 50000
#define DD 128
#define EE 800000
#define EPSL 1e-5f

#define SCH 512
#define SNB ((NN + SCH - 1) / SCH)   // 98

// GEMM tiling (fp16 MMA, full-K resident)
#define BM 128
#define APH 136                       // As row stride in halves (272B rows)
#define WPH 136                       // Ws row stride in halves
#define SMEM_BYTES ((BM * APH + DD * WPH) * 2)   // 69632 B

// ---------------- scratch (device globals; no allocation allowed) -------------
__device__ float  g_dinv[NN];
__device__ __half g_tmpA[NN * DD];    // fp16 raw messages: ReLU(LN(h))@W
__device__ __half g_tmpB[NN * DD];
__device__ float  g_x1[NN * DD];      // x after layer0 + residual
__device__ float  g_h2[NN * DD];      // layer1 output
__device__ __half g_W16a[DD * DD];    // fp16 weights (pre-converted)
__device__ __half g_W16b[DD * DD];
__device__ __half g_W16c[DD * DD];
__device__ int    g_cnt[NN];
__device__ int    g_start[NN];
__device__ int    g_cursor[NN];
__device__ int    g_esrc[EE];
__device__ int    g_csum[SNB];

// ---------------- weight fp16 pre-conversion -----------------------------------
__global__ void k_wcvt(const float* __restrict__ W, __half* __restrict__ W16) {
    int idx = blockIdx.x * blockDim.x + threadIdx.x;   // over DD*DD/4
    if (idx >= DD * DD / 4) return;
    float4 wv = ((const float4*)W)[idx];
    __half2 p0 = __floats2half2_rn(wv.x, wv.y);
    __half2 p1 = __floats2half2_rn(wv.z, wv.w);
    uint2 u;
    u.x = *(uint32_t*)&p0;
    u.y = *(uint32_t*)&p1;
    ((uint2*)W16)[idx] = u;
}

// ---------------- CSR build ----------------------------------------------------
__global__ void k_zero() {
    int i = blockIdx.x * blockDim.x + threadIdx.x;
    if (i < NN) g_cnt[i] = 0;
}

__global__ void k_hist(const int* __restrict__ dst) {
    int e = blockIdx.x * blockDim.x + threadIdx.x;
    if (e < EE) atomicAdd(&g_cnt[dst[e]], 1);
}

__global__ void k_dinv() {
    int i = blockIdx.x * blockDim.x + threadIdx.x;
    if (i < NN) g_dinv[i] = rsqrtf(1.0f + (float)g_cnt[i]);
}

__global__ void __launch_bounds__(SCH) k_scan_a() {
    __shared__ int sm[SCH];
    int t = threadIdx.x;
    int i = blockIdx.x * SCH + t;
    sm[t] = (i < NN) ? g_cnt[i] : 0;
    __syncthreads();
    for (int off = SCH / 2; off > 0; off >>= 1) {
        if (t < off) sm[t] += sm[t + off];
        __syncthreads();
    }
    if (t == 0) g_csum[blockIdx.x] = sm[0];
}

__global__ void __launch_bounds__(SCH) k_scan_c() {
    __shared__ int sm[SCH];
    __shared__ int base;
    int t = threadIdx.x;
    int i = blockIdx.x * SCH + t;
    int v = (i < NN) ? g_cnt[i] : 0;
    sm[t] = v;
    if (t == 0) {
        int run = 0;
        for (int j = 0; j < blockIdx.x; j++) run += g_csum[j];
        base = run;
    }
    __syncthreads();
    for (int off = 1; off < SCH; off <<= 1) {
        int x = (t >= off) ? sm[t - off] : 0;
        __syncthreads();
        sm[t] += x;
        __syncthreads();
    }
    if (i < NN) {
        int excl = sm[t] - v + base;
        g_start[i] = excl;
        g_cursor[i] = excl;
    }
}

__global__ void k_bucket(const int* __restrict__ src, const int* __restrict__ dst) {
    int e = blockIdx.x * blockDim.x + threadIdx.x;
    if (e < EE) {
        int pos = atomicAdd(&g_cursor[dst[e]], 1);
        g_esrc[pos] = src[e];
    }
}

// ---------------- MMA helpers ---------------------------------------------------
__device__ __forceinline__ uint32_t smem_u32(const void* p) {
    return (uint32_t)__cvta_generic_to_shared(p);
}

__device__ __forceinline__ void ldmatrix_x4(uint32_t& r0, uint32_t& r1,
                                            uint32_t& r2, uint32_t& r3, uint32_t addr) {
    asm volatile("ldmatrix.sync.aligned.m8n8.x4.shared.b16 {%0,%1,%2,%3}, [%4];"
                 : "=r"(r0), "=r"(r1), "=r"(r2), "=r"(r3) : "r"(addr));
}

__device__ __forceinline__ void ldmatrix_x2_trans(uint32_t& r0, uint32_t& r1, uint32_t addr) {
    asm volatile("ldmatrix.sync.aligned.m8n8.x2.trans.shared.b16 {%0,%1}, [%2];"
                 : "=r"(r0), "=r"(r1) : "r"(addr));
}

__device__ __forceinline__ void mma_f16(float4& c, uint32_t a0, uint32_t a1,
                                        uint32_t a2, uint32_t a3,
                                        uint32_t b0, uint32_t b1) {
    asm volatile("mma.sync.aligned.m16n8k16.row.col.f32.f16.f16.f32 "
                 "{%0,%1,%2,%3}, {%4,%5,%6,%7}, {%8,%9}, {%0,%1,%2,%3};"
                 : "+f"(c.x), "+f"(c.y), "+f"(c.z), "+f"(c.w)
                 : "r"(a0), "r"(a1), "r"(a2), "r"(a3), "r"(b0), "r"(b1));
}

// ---------------- fused LN + ReLU + fp16 GEMM ----------------------------------
// tout[i] = half( ReLU( LN(h_i)*g + bt ) @ W )        (NO dinv here)
// Block 512 thr (16 warps); tile M=128 x N=128; warp tile m32 x n32.
__global__ void __launch_bounds__(512) k_ln_gemm(const float* __restrict__ h,
                          const float* __restrict__ g,
                          const float* __restrict__ bt,
                          const __half* __restrict__ W16,
                          __half* __restrict__ tout) {
    extern __shared__ __half smh[];
    __half* As = smh;                 // [BM][APH] halves
    __half* Ws = smh + BM * APH;      // [DD][WPH] halves

    int tid = threadIdx.x;
    int lane = tid & 31;
    int w = tid >> 5;           // 0..15
    int qid = lane >> 2;        // 0..7
    int tq = lane & 3;          // 0..3
    int row0 = blockIdx.x * BM;

    // --- stage full W (fp16, 32KB) -> Ws ---
    for (int idx = tid; idx < DD * DD / 8; idx += 512) {
        int kk = idx >> 4;            // 16 uint4 per row
        int c8 = (idx & 15) * 8;
        uint4 u = ((const uint4*)W16)[idx];
        *(uint4*)(Ws + kk * WPH + c8) = u;
    }

    // --- LN + ReLU -> fp16 As; warp w handles rows w, w+16, ..., w+112 ---
    for (int r = w; r < BM; r += 16) {
        int row = row0 + r;
        float4 v = make_float4(0.f, 0.f, 0.f, 0.f);
        if (row < NN) v = ((const float4*)(h + (size_t)row * DD))[lane];
        float s = v.x + v.y + v.z + v.w;
        #pragma unroll
        for (int o = 16; o; o >>= 1) s += __shfl_xor_sync(0xffffffffu, s, o);
        float mu = s * (1.0f / DD);
        float dx = v.x - mu, dy = v.y - mu, dz = v.z - mu, dw = v.w - mu;
        float q = dx * dx + dy * dy + dz * dz + dw * dw;
        #pragma unroll
        for (int o = 16; o; o >>= 1) q += __shfl_xor_sync(0xffffffffu, q, o);
        float rstd = rsqrtf(q * (1.0f / DD) + EPSL);
        float4 gg = ((const float4*)g)[lane];
        float4 bb = ((const float4*)bt)[lane];
        __half2 h2a = __floats2half2_rn(fmaxf(fmaf(dx * rstd, gg.x, bb.x), 0.f),
                                        fmaxf(fmaf(dy * rstd, gg.y, bb.y), 0.f));
        __half2 h2b = __floats2half2_rn(fmaxf(fmaf(dz * rstd, gg.z, bb.z), 0.f),
                                        fmaxf(fmaf(dw * rstd, gg.w, bb.w), 0.f));
        uint2 u;
        u.x = *(uint32_t*)&h2a;
        u.y = *(uint32_t*)&h2b;
        *(uint2*)(As + r * APH + lane * 4) = u;
    }

    __syncthreads();   // the only barrier

    // warp tile: warp_m 0..3 (m32), warp_n 0..3 (n32)
    int warp_m = w & 3;
    int warp_n = w >> 2;
    int m0 = warp_m * 32;
    int nb = warp_n * 32;

    float4 c[2][4];
    #pragma unroll
    for (int mt = 0; mt < 2; mt++)
        #pragma unroll
        for (int nt = 0; nt < 4; nt++) c[mt][nt] = make_float4(0.f, 0.f, 0.f, 0.f);

    // ldmatrix lane addressing
    int a_row = (lane & 7) + 8 * ((lane >> 3) & 1);
    int a_col8 = 8 * (lane >> 4);
    int b_row = lane & 15;

    #pragma unroll
    for (int ks = 0; ks < DD / 16; ks++) {
        int kb = ks * 16;
        uint32_t a[2][4];
        #pragma unroll
        for (int mt = 0; mt < 2; mt++) {
            uint32_t addr = smem_u32(As + (m0 + mt * 16 + a_row) * APH + kb + a_col8);
            ldmatrix_x4(a[mt][0], a[mt][1], a[mt][2], a[mt][3], addr);
        }
        uint32_t b[4][2];
        #pragma unroll
        for (int nt = 0; nt < 4; nt++) {
            int nbf = nb + nt * 8;
            uint32_t addr = smem_u32(Ws + (kb + b_row) * WPH + nbf);
            ldmatrix_x2_trans(b[nt][0], b[nt][1], addr);
        }
        #pragma unroll
        for (int mt = 0; mt < 2; mt++)
            #pragma unroll
            for (int nt = 0; nt < 4; nt++)
                mma_f16(c[mt][nt], a[mt][0], a[mt][1], a[mt][2], a[mt][3],
                        b[nt][0], b[nt][1]);
    }

    // epilogue: write half2 pairs (no dinv)
    #pragma unroll
    for (int mt = 0; mt < 2; mt++) {
        int ra = row0 + m0 + mt * 16 + qid;
        int rb = ra + 8;
        #pragma unroll
        for (int nt = 0; nt < 4; nt++) {
            int col = nb + nt * 8 + 2 * tq;
            if (ra < NN) {
                __half2 o = __floats2half2_rn(c[mt][nt].x, c[mt][nt].y);
                *(uint32_t*)(tout + (size_t)ra * DD + col) = *(uint32_t*)&o;
            }
            if (rb < NN) {
                __half2 o = __floats2half2_rn(c[mt][nt].z, c[mt][nt].w);
                *(uint32_t*)(tout + (size_t)rb * DD + col) = *(uint32_t*)&o;
            }
        }
    }
}

// ---------------- per-node gather accumulate (fp16 raw -> fp32 out) ------------
// out[i] = b + dinv[i]*( dinv[i]*raw[i] + sum_e dinv[src_e]*raw[src_e] ) (+ res)
__global__ void __launch_bounds__(256) k_accum(const __half* __restrict__ tin,
                        float* __restrict__ out,
                        const float* __restrict__ b,
                        const float* __restrict__ res) {
    int node = (blockIdx.x * blockDim.x + threadIdx.x) >> 5;
    int lane = threadIdx.x & 31;
    if (node >= NN) return;

    const uint2* T = (const uint2*)tin;   // 4 halves per lane
    int s0 = g_start[node];
    int cnt = g_cnt[node];
    float dvn = g_dinv[node];

    float4 a[8];
    {
        uint2 u = T[(size_t)node * 32 + lane];
        float2 f0 = __half22float2(*(__half2*)&u.x);
        float2 f1 = __half22float2(*(__half2*)&u.y);
        a[0] = make_float4(dvn * f0.x, dvn * f0.y, dvn * f1.x, dvn * f1.y);
    }
    #pragma unroll
    for (int j = 1; j < 8; j++) a[j] = make_float4(0.f, 0.f, 0.f, 0.f);

    int e = 0;
    for (; e + 8 <= cnt; e += 8) {
        int idx[8];
        float dj[8];
        #pragma unroll
        for (int j = 0; j < 8; j++) idx[j] = g_esrc[s0 + e + j];
        #pragma unroll
        for (int j = 0; j < 8; j++) dj[j] = g_dinv[idx[j]];
        #pragma unroll
        for (int j = 0; j < 8; j++) {
            uint2 u = T[(size_t)idx[j] * 32 + lane];
            float2 f0 = __half22float2(*(__half2*)&u.x);
            float2 f1 = __half22float2(*(__half2*)&u.y);
            a[j].x = fmaf(dj[j], f0.x, a[j].x);
            a[j].y = fmaf(dj[j], f0.y, a[j].y);
            a[j].z = fmaf(dj[j], f1.x, a[j].z);
            a[j].w = fmaf(dj[j], f1.y, a[j].w);
        }
    }
    for (; e < cnt; e++) {
        int i0 = g_esrc[s0 + e];
        float d0 = g_dinv[i0];
        uint2 u = T[(size_t)i0 * 32 + lane];
        float2 f0 = __half22float2(*(__half2*)&u.x);
        float2 f1 = __half22float2(*(__half2*)&u.y);
        a[0].x = fmaf(d0, f0.x, a[0].x);
        a[0].y = fmaf(d0, f0.y, a[0].y);
        a[0].z = fmaf(d0, f1.x, a[0].z);
        a[0].w = fmaf(d0, f1.y, a[0].w);
    }
    #pragma unroll
    for (int j = 1; j < 8; j++) {
        a[0].x += a[j].x; a[0].y += a[j].y; a[0].z += a[j].z; a[0].w += a[j].w;
    }

    float4 bb = ((const float4*)b)[lane];
    float4 o;
    o.x = fmaf(dvn, a[0].x, bb.x);
    o.y = fmaf(dvn, a[0].y, bb.y);
    o.z = fmaf(dvn, a[0].z, bb.z);
    o.w = fmaf(dvn, a[0].w, bb.w);
    if (res) {
        float4 r = ((const float4*)(res))[(size_t)node * 32 + lane];
        o.x += r.x; o.y += r.y; o.z += r.z; o.w += r.w;
    }
    ((float4*)out)[(size_t)node * 32 + lane] = o;
}

// ---------------- launch ------------------------------------------------------
extern "C" void kernel_launch(void* const* d_in, const int* in_sizes, int n_in,
                              void* d_out, int out_size) {
    const float* x   = (const float*)d_in[0];
    const int*   ei  = (const int*)d_in[1];
    const int*   src = ei;
    const int*   dst = ei + EE;
    const float* lng0 = (const float*)d_in[2];
    const float* lnb0 = (const float*)d_in[3];
    const float* W0   = (const float*)d_in[4];
    const float* b0   = (const float*)d_in[5];
    const float* lng1 = (const float*)d_in[6];
    const float* lnb1 = (const float*)d_in[7];
    const float* W1   = (const float*)d_in[8];
    const float* b1   = (const float*)d_in[9];
    const float* lng2 = (const float*)d_in[10];
    const float* lnb2 = (const float*)d_in[11];
    const float* W2   = (const float*)d_in[12];
    const float* b2   = (const float*)d_in[13];
    float* out = (float*)d_out;

    __half* d_tA; cudaGetSymbolAddress((void**)&d_tA, g_tmpA);
    __half* d_tB; cudaGetSymbolAddress((void**)&d_tB, g_tmpB);
    float*  d_x1; cudaGetSymbolAddress((void**)&d_x1, g_x1);
    float*  d_h2; cudaGetSymbolAddress((void**)&d_h2, g_h2);
    __half* d_Wa; cudaGetSymbolAddress((void**)&d_Wa, g_W16a);
    __half* d_Wb; cudaGetSymbolAddress((void**)&d_Wb, g_W16b);
    __half* d_Wc; cudaGetSymbolAddress((void**)&d_Wc, g_W16c);

    cudaFuncSetAttribute(k_ln_gemm, cudaFuncAttributeMaxDynamicSharedMemorySize, SMEM_BYTES);

    static cudaStream_t s2 = nullptr;
    static cudaEvent_t evF = nullptr, evJ = nullptr;
    if (!s2) {
        cudaStreamCreateWithFlags(&s2, cudaStreamNonBlocking);
        cudaEventCreateWithFlags(&evF, cudaEventDisableTiming);
        cudaEventCreateWithFlags(&evJ, cudaEventDisableTiming);
    }

    const int gemm_blocks = (NN + BM - 1) / BM;   // 391
    const int acc_blocks = (NN * 32 + 255) / 256;
    const int wcvt_blocks = (DD * DD / 4 + 255) / 256;

    // main stream: weight conversions (GEMMs depend on these)
    k_wcvt<<<wcvt_blocks, 256>>>(W0, d_Wa);
    k_wcvt<<<wcvt_blocks, 256>>>(W1, d_Wb);
    k_wcvt<<<wcvt_blocks, 256>>>(W2, d_Wc);

    // fork: CSR prep on s2, concurrent with GEMM0 on main stream
    cudaEventRecord(evF, 0);
    cudaStreamWaitEvent(s2, evF, 0);
    k_zero<<<(NN + 255) / 256, 256, 0, s2>>>();
    k_hist<<<(EE + 255) / 256, 256, 0, s2>>>(dst);
    k_dinv<<<(NN + 255) / 256, 256, 0, s2>>>();
    k_scan_a<<<SNB, SCH, 0, s2>>>();
    k_scan_c<<<SNB, SCH, 0, s2>>>();
    k_bucket<<<(EE + 255) / 256, 256, 0, s2>>>(src, dst);
    cudaEventRecord(evJ, s2);

    // main: layer 0 GEMM (no prep dependency now): x -> tA (raw)
    k_ln_gemm<<<gemm_blocks, 512, SMEM_BYTES>>>(x, lng0, lnb0, d_Wa, d_tA);

    // join before accum
    cudaStreamWaitEvent(0, evJ, 0);

    // layer 0 accum: tA (+x) -> x1
    k_accum<<<acc_blocks, 256>>>(d_tA, d_x1, b0, x);

    // layer 1: x1 -> tB ; accum -> h2
    k_ln_gemm<<<gemm_blocks, 512, SMEM_BYTES>>>(d_x1, lng1, lnb1, d_Wb, d_tB);
    k_accum<<<acc_blocks, 256>>>(d_tB, d_h2, b1, nullptr);

    // layer 2: h2 -> tA ; accum (+x1) -> out
    k_ln_gemm<<<gemm_blocks, 512, SMEM_BYTES>>>(d_h2, lng2, lnb2, d_Wc, d_tA);
    k_accum<<<acc_blocks, 256>>>(d_tA, out, b2, d_x1);
}

// round 15
// speedup vs baseline: 1.3154x; 1.3154x over previous
#include <cuda_runtime.h>
#include <cuda_fp16.h>
#include <cstdint>

#define NN 50000
#define DD 128
#define EE 800000
#define EPSL 1e-5f

#define SCH 512
#define SNB ((NN + SCH - 1) / SCH)   // 98

// GEMM tiling (fp16 MMA, full-K resident)
#define BM 128
#define APH 136                       // As row stride in halves (272B rows)
#define WPH 136                       // Ws row stride in halves
#define SMEM_BYTES ((BM * APH + DD * WPH) * 2)   // 69632 B

// ---------------- scratch (device globals; no allocation allowed) -------------
__device__ float  g_dinv[NN];
__device__ __half g_tmpA[NN * DD];    // fp16 messages: dinv[i]*(ReLU(LN(h))@W)
__device__ __half g_tmpB[NN * DD];
__device__ float  g_x1[NN * DD];      // x after layer0 + residual
__device__ float  g_h2[NN * DD];      // layer1 output
__device__ __half g_W16[3 * DD * DD]; // fp16 weights (pre-converted, 3 matrices)
__device__ int    g_cnt[NN];
__device__ int    g_start[NN];
__device__ int    g_cursor[NN];
__device__ int    g_esrc[EE];
__device__ int    g_csum[SNB];

// ---------------- weight fp16 pre-conversion (all 3 in one launch) -------------
__global__ void k_wcvt(const float* __restrict__ W0, const float* __restrict__ W1,
                       const float* __restrict__ W2) {
    int idx = blockIdx.x * blockDim.x + threadIdx.x;   // over 3*DD*DD/4
    if (idx >= 3 * DD * DD / 4) return;
    int which = idx / (DD * DD / 4);
    int i = idx % (DD * DD / 4);
    const float* W = (which == 0) ? W0 : (which == 1) ? W1 : W2;
    float4 wv = ((const float4*)W)[i];
    __half2 p0 = __floats2half2_rn(wv.x, wv.y);
    __half2 p1 = __floats2half2_rn(wv.z, wv.w);
    uint2 u;
    u.x = *(uint32_t*)&p0;
    u.y = *(uint32_t*)&p1;
    ((uint2*)g_W16)[idx] = u;
}

// ---------------- CSR build ----------------------------------------------------
__global__ void k_zero() {
    int i = blockIdx.x * blockDim.x + threadIdx.x;
    if (i < NN) g_cnt[i] = 0;
}

__global__ void k_hist(const int* __restrict__ dst) {
    int e = blockIdx.x * blockDim.x + threadIdx.x;
    if (e < EE) atomicAdd(&g_cnt[dst[e]], 1);
}

// per-chunk sums + dinv (folded)
__global__ void __launch_bounds__(SCH) k_scan_a() {
    __shared__ int sm[SCH];
    int t = threadIdx.x;
    int i = blockIdx.x * SCH + t;
    int v = (i < NN) ? g_cnt[i] : 0;
    sm[t] = v;
    if (i < NN) g_dinv[i] = rsqrtf(1.0f + (float)v);
    __syncthreads();
    for (int off = SCH / 2; off > 0; off >>= 1) {
        if (t < off) sm[t] += sm[t + off];
        __syncthreads();
    }
    if (t == 0) g_csum[blockIdx.x] = sm[0];
}

__global__ void __launch_bounds__(SCH) k_scan_c() {
    __shared__ int sm[SCH];
    __shared__ int base;
    int t = threadIdx.x;
    int i = blockIdx.x * SCH + t;
    int v = (i < NN) ? g_cnt[i] : 0;
    sm[t] = v;
    if (t == 0) {
        int run = 0;
        for (int j = 0; j < blockIdx.x; j++) run += g_csum[j];
        base = run;
    }
    __syncthreads();
    for (int off = 1; off < SCH; off <<= 1) {
        int x = (t >= off) ? sm[t - off] : 0;
        __syncthreads();
        sm[t] += x;
        __syncthreads();
    }
    if (i < NN) {
        int excl = sm[t] - v + base;
        g_start[i] = excl;
        g_cursor[i] = excl;
    }
}

__global__ void k_bucket(const int* __restrict__ src, const int* __restrict__ dst) {
    int e = blockIdx.x * blockDim.x + threadIdx.x;
    if (e < EE) {
        int pos = atomicAdd(&g_cursor[dst[e]], 1);
        g_esrc[pos] = src[e];
    }
}

// ---------------- MMA helpers ---------------------------------------------------
__device__ __forceinline__ uint32_t smem_u32(const void* p) {
    return (uint32_t)__cvta_generic_to_shared(p);
}

__device__ __forceinline__ void ldmatrix_x4(uint32_t& r0, uint32_t& r1,
                                            uint32_t& r2, uint32_t& r3, uint32_t addr) {
    asm volatile("ldmatrix.sync.aligned.m8n8.x4.shared.b16 {%0,%1,%2,%3}, [%4];"
                 : "=r"(r0), "=r"(r1), "=r"(r2), "=r"(r3) : "r"(addr));
}

__device__ __forceinline__ void ldmatrix_x2_trans(uint32_t& r0, uint32_t& r1, uint32_t addr) {
    asm volatile("ldmatrix.sync.aligned.m8n8.x2.trans.shared.b16 {%0,%1}, [%2];"
                 : "=r"(r0), "=r"(r1) : "r"(addr));
}

__device__ __forceinline__ void mma_f16(float4& c, uint32_t a0, uint32_t a1,
                                        uint32_t a2, uint32_t a3,
                                        uint32_t b0, uint32_t b1) {
    asm volatile("mma.sync.aligned.m16n8k16.row.col.f32.f16.f16.f32 "
                 "{%0,%1,%2,%3}, {%4,%5,%6,%7}, {%8,%9}, {%0,%1,%2,%3};"
                 : "+f"(c.x), "+f"(c.y), "+f"(c.z), "+f"(c.w)
                 : "r"(a0), "r"(a1), "r"(a2), "r"(a3), "r"(b0), "r"(b1));
}

// ---------------- fused LN + ReLU + fp16 GEMM + dinv prescale ------------------
// tout[i] = half( dinv[i] * ( ReLU( LN(h_i)*g + bt ) @ W ) )
// Block 512 thr (16 warps); tile M=128 x N=128; warp tile m32 x n32.
__global__ void __launch_bounds__(512) k_ln_gemm(const float* __restrict__ h,
                          const float* __restrict__ g,
                          const float* __restrict__ bt,
                          const __half* __restrict__ W16,
                          __half* __restrict__ tout) {
    extern __shared__ __half smh[];
    __half* As = smh;                 // [BM][APH] halves
    __half* Ws = smh + BM * APH;      // [DD][WPH] halves

    int tid = threadIdx.x;
    int lane = tid & 31;
    int w = tid >> 5;           // 0..15
    int qid = lane >> 2;        // 0..7
    int tq = lane & 3;          // 0..3
    int row0 = blockIdx.x * BM;

    // --- stage full W (fp16, 32KB) -> Ws ---
    for (int idx = tid; idx < DD * DD / 8; idx += 512) {
        int kk = idx >> 4;            // 16 uint4 per row
        int c8 = (idx & 15) * 8;
        uint4 u = ((const uint4*)W16)[idx];
        *(uint4*)(Ws + kk * WPH + c8) = u;
    }

    // --- LN + ReLU -> fp16 As; warp w handles rows w, w+16, ..., w+112 ---
    for (int r = w; r < BM; r += 16) {
        int row = row0 + r;
        float4 v = make_float4(0.f, 0.f, 0.f, 0.f);
        if (row < NN) v = ((const float4*)(h + (size_t)row * DD))[lane];
        float s = v.x + v.y + v.z + v.w;
        #pragma unroll
        for (int o = 16; o; o >>= 1) s += __shfl_xor_sync(0xffffffffu, s, o);
        float mu = s * (1.0f / DD);
        float dx = v.x - mu, dy = v.y - mu, dz = v.z - mu, dw = v.w - mu;
        float q = dx * dx + dy * dy + dz * dz + dw * dw;
        #pragma unroll
        for (int o = 16; o; o >>= 1) q += __shfl_xor_sync(0xffffffffu, q, o);
        float rstd = rsqrtf(q * (1.0f / DD) + EPSL);
        float4 gg = ((const float4*)g)[lane];
        float4 bb = ((const float4*)bt)[lane];
        __half2 h2a = __floats2half2_rn(fmaxf(fmaf(dx * rstd, gg.x, bb.x), 0.f),
                                        fmaxf(fmaf(dy * rstd, gg.y, bb.y), 0.f));
        __half2 h2b = __floats2half2_rn(fmaxf(fmaf(dz * rstd, gg.z, bb.z), 0.f),
                                        fmaxf(fmaf(dw * rstd, gg.w, bb.w), 0.f));
        uint2 u;
        u.x = *(uint32_t*)&h2a;
        u.y = *(uint32_t*)&h2b;
        *(uint2*)(As + r * APH + lane * 4) = u;
    }

    __syncthreads();   // the only barrier

    // warp tile: warp_m 0..3 (m32), warp_n 0..3 (n32)
    int warp_m = w & 3;
    int warp_n = w >> 2;
    int m0 = warp_m * 32;
    int nb = warp_n * 32;

    float4 c[2][4];
    #pragma unroll
    for (int mt = 0; mt < 2; mt++)
        #pragma unroll
        for (int nt = 0; nt < 4; nt++) c[mt][nt] = make_float4(0.f, 0.f, 0.f, 0.f);

    // ldmatrix lane addressing
    int a_row = (lane & 7) + 8 * ((lane >> 3) & 1);
    int a_col8 = 8 * (lane >> 4);
    int b_row = lane & 15;

    #pragma unroll
    for (int ks = 0; ks < DD / 16; ks++) {
        int kb = ks * 16;
        uint32_t a[2][4];
        #pragma unroll
        for (int mt = 0; mt < 2; mt++) {
            uint32_t addr = smem_u32(As + (m0 + mt * 16 + a_row) * APH + kb + a_col8);
            ldmatrix_x4(a[mt][0], a[mt][1], a[mt][2], a[mt][3], addr);
        }
        uint32_t b[4][2];
        #pragma unroll
        for (int nt = 0; nt < 4; nt++) {
            int nbf = nb + nt * 8;
            uint32_t addr = smem_u32(Ws + (kb + b_row) * WPH + nbf);
            ldmatrix_x2_trans(b[nt][0], b[nt][1], addr);
        }
        #pragma unroll
        for (int mt = 0; mt < 2; mt++)
            #pragma unroll
            for (int nt = 0; nt < 4; nt++)
                mma_f16(c[mt][nt], a[mt][0], a[mt][1], a[mt][2], a[mt][3],
                        b[nt][0], b[nt][1]);
    }

    // epilogue: scale by dinv[row], write half2 pairs
    #pragma unroll
    for (int mt = 0; mt < 2; mt++) {
        int ra = row0 + m0 + mt * 16 + qid;
        int rb = ra + 8;
        float dva = (ra < NN) ? g_dinv[ra] : 0.f;
        float dvb = (rb < NN) ? g_dinv[rb] : 0.f;
        #pragma unroll
        for (int nt = 0; nt < 4; nt++) {
            int col = nb + nt * 8 + 2 * tq;
            if (ra < NN) {
                __half2 o = __floats2half2_rn(c[mt][nt].x * dva, c[mt][nt].y * dva);
                *(uint32_t*)(tout + (size_t)ra * DD + col) = *(uint32_t*)&o;
            }
            if (rb < NN) {
                __half2 o = __floats2half2_rn(c[mt][nt].z * dvb, c[mt][nt].w * dvb);
                *(uint32_t*)(tout + (size_t)rb * DD + col) = *(uint32_t*)&o;
            }
        }
    }
}

// ---------------- per-node gather accumulate (fp16 messages -> fp32 out) -------
// out[i] = b + dinv[i]*(tin[i] + sum_{e in CSR[i]} tin[src_e]) (+ res[i])
__global__ void __launch_bounds__(256) k_accum(const __half* __restrict__ tin,
                        float* __restrict__ out,
                        const float* __restrict__ b,
                        const float* __restrict__ res) {
    int node = (blockIdx.x * blockDim.x + threadIdx.x) >> 5;
    int lane = threadIdx.x & 31;
    if (node >= NN) return;

    const uint2* T = (const uint2*)tin;   // 4 halves per lane
    int s0 = g_start[node];
    int cnt = g_cnt[node];

    float4 a[8];
    {
        uint2 u = T[(size_t)node * 32 + lane];
        float2 f0 = __half22float2(*(__half2*)&u.x);
        float2 f1 = __half22float2(*(__half2*)&u.y);
        a[0] = make_float4(f0.x, f0.y, f1.x, f1.y);
    }
    #pragma unroll
    for (int j = 1; j < 8; j++) a[j] = make_float4(0.f, 0.f, 0.f, 0.f);

    int e = 0;
    for (; e + 8 <= cnt; e += 8) {
        int idx[8];
        #pragma unroll
        for (int j = 0; j < 8; j++) idx[j] = g_esrc[s0 + e + j];
        #pragma unroll
        for (int j = 0; j < 8; j++) {
            uint2 u = T[(size_t)idx[j] * 32 + lane];
            float2 f0 = __half22float2(*(__half2*)&u.x);
            float2 f1 = __half22float2(*(__half2*)&u.y);
            a[j].x += f0.x; a[j].y += f0.y; a[j].z += f1.x; a[j].w += f1.y;
        }
    }
    for (; e < cnt; e++) {
        int i0 = g_esrc[s0 + e];
        uint2 u = T[(size_t)i0 * 32 + lane];
        float2 f0 = __half22float2(*(__half2*)&u.x);
        float2 f1 = __half22float2(*(__half2*)&u.y);
        a[0].x += f0.x; a[0].y += f0.y; a[0].z += f1.x; a[0].w += f1.y;
    }
    #pragma unroll
    for (int j = 1; j < 8; j++) {
        a[0].x += a[j].x; a[0].y += a[j].y; a[0].z += a[j].z; a[0].w += a[j].w;
    }

    float dv = g_dinv[node];
    float4 bb = ((const float4*)b)[lane];
    float4 o;
    o.x = fmaf(dv, a[0].x, bb.x);
    o.y = fmaf(dv, a[0].y, bb.y);
    o.z = fmaf(dv, a[0].z, bb.z);
    o.w = fmaf(dv, a[0].w, bb.w);
    if (res) {
        float4 r = ((const float4*)(res))[(size_t)node * 32 + lane];
        o.x += r.x; o.y += r.y; o.z += r.z; o.w += r.w;
    }
    ((float4*)out)[(size_t)node * 32 + lane] = o;
}

// ---------------- launch ------------------------------------------------------
extern "C" void kernel_launch(void* const* d_in, const int* in_sizes, int n_in,
                              void* d_out, int out_size) {
    const float* x   = (const float*)d_in[0];
    const int*   ei  = (const int*)d_in[1];
    const int*   src = ei;
    const int*   dst = ei + EE;
    const float* lng0 = (const float*)d_in[2];
    const float* lnb0 = (const float*)d_in[3];
    const float* W0   = (const float*)d_in[4];
    const float* b0   = (const float*)d_in[5];
    const float* lng1 = (const float*)d_in[6];
    const float* lnb1 = (const float*)d_in[7];
    const float* W1   = (const float*)d_in[8];
    const float* b1   = (const float*)d_in[9];
    const float* lng2 = (const float*)d_in[10];
    const float* lnb2 = (const float*)d_in[11];
    const float* W2   = (const float*)d_in[12];
    const float* b2   = (const float*)d_in[13];
    float* out = (float*)d_out;

    __half* d_tA; cudaGetSymbolAddress((void**)&d_tA, g_tmpA);
    __half* d_tB; cudaGetSymbolAddress((void**)&d_tB, g_tmpB);
    float*  d_x1; cudaGetSymbolAddress((void**)&d_x1, g_x1);
    float*  d_h2; cudaGetSymbolAddress((void**)&d_h2, g_h2);
    __half* d_W16base; cudaGetSymbolAddress((void**)&d_W16base, g_W16);
    __half* d_Wa = d_W16base;
    __half* d_Wb = d_W16base + DD * DD;
    __half* d_Wc = d_W16base + 2 * DD * DD;

    cudaFuncSetAttribute(k_ln_gemm, cudaFuncAttributeMaxDynamicSharedMemorySize, SMEM_BYTES);

    const int gemm_blocks = (NN + BM - 1) / BM;   // 391
    const int acc_blocks = (NN * 32 + 255) / 256;
    const int wcvt_blocks = (3 * DD * DD / 4 + 255) / 256;

    // prep: weights + counts + dinv (single stream)
    k_wcvt<<<wcvt_blocks, 256>>>(W0, W1, W2);
    k_zero<<<(NN + 255) / 256, 256>>>();
    k_hist<<<(EE + 255) / 256, 256>>>(dst);
    k_scan_a<<<SNB, SCH>>>();      // dinv + chunk sums

    // layer 0 GEMM (launch #5 -> near ncu profile slot): x -> tA
    k_ln_gemm<<<gemm_blocks, 512, SMEM_BYTES>>>(x, lng0, lnb0, d_Wa, d_tA);

    // prep part 2 (CSR for accum)
    k_scan_c<<<SNB, SCH>>>();
    k_bucket<<<(EE + 255) / 256, 256>>>(src, dst);

    // layer 0 accum: tA (+x) -> x1
    k_accum<<<acc_blocks, 256>>>(d_tA, d_x1, b0, x);

    // layer 1: x1 -> tB ; accum -> h2
    k_ln_gemm<<<gemm_blocks, 512, SMEM_BYTES>>>(d_x1, lng1, lnb1, d_Wb, d_tB);
    k_accum<<<acc_blocks, 256>>>(d_tB, d_h2, b1, nullptr);

    // layer 2: h2 -> tA ; accum (+x1) -> out
    k_ln_gemm<<<gemm_blocks, 512, SMEM_BYTES>>>(d_h2, lng2, lnb2, d_Wc, d_tA);
    k_accum<<<acc_blocks, 256>>>(d_tA, out, b2, d_x1);
}